// round 11
// baseline (speedup 1.0000x reference)
#include <cuda_runtime.h>
#include <cuda_fp16.h>
#include <math.h>
#include <stdint.h>

#define BSZ   2048
#define DETER 8192
#define STOCH 1024
#define ACTD  32
#define HID   1024
#define GRP   8
#define DPG   1024
#define EPSV  1e-6f

// ---------------- scratch (static device arrays; no allocations) -------------
__device__ float  g_xc [BSZ * 3 * HID];
__device__ __half g_Hh [BSZ * DETER];
__device__ __half g_Xh [BSZ * GRP * 3 * DPG];
__device__ __half g_xch[BSZ * 3 * HID];
__device__ __half g_hnh[BSZ * DETER];
__device__ __half g_deterh[BSZ * DETER];
__device__ __half g_stochh[BSZ * STOCH];
__device__ __half g_W1T  [HID * DETER];
__device__ __half g_W2T  [HID * STOCH];
__device__ __half g_WdynT[GRP * DPG * 4096];
__device__ __half g_WoutT[GRP * 3 * DPG * DPG];

// ---------------- helpers ----------------------------------------------------
__device__ __forceinline__ void mma_f16(float& c0, float& c1, float& c2, float& c3,
                                        uint32_t a0, uint32_t a1, uint32_t a2, uint32_t a3,
                                        uint32_t b0, uint32_t b1) {
    asm("mma.sync.aligned.m16n8k16.row.col.f32.f16.f16.f32 "
        "{%0,%1,%2,%3},{%4,%5,%6,%7},{%8,%9},{%0,%1,%2,%3};"
        : "+f"(c0), "+f"(c1), "+f"(c2), "+f"(c3)
        : "r"(a0), "r"(a1), "r"(a2), "r"(a3), "r"(b0), "r"(b1));
}

#define LDSM4(r0, r1, r2, r3, a) \
    asm volatile("ldmatrix.sync.aligned.m8n8.x4.shared.b16 {%0,%1,%2,%3}, [%4];" \
                 : "=r"(r0), "=r"(r1), "=r"(r2), "=r"(r3) : "r"(a))

#define CP_ASYNC16(s, g) \
    asm volatile("cp.async.cg.shared.global [%0], [%1], 16;" :: "r"(s), "l"(g) : "memory")
#define CP_COMMIT() asm volatile("cp.async.commit_group;" ::: "memory")
#define CP_WAIT3()  asm volatile("cp.async.wait_group 3;" ::: "memory")

__device__ __forceinline__ float block_sum(float v) {
    __shared__ float red[32];
    int lane = threadIdx.x & 31, w = threadIdx.x >> 5;
    #pragma unroll
    for (int o = 16; o; o >>= 1) v += __shfl_xor_sync(0xffffffffu, v, o);
    if (lane == 0) red[w] = v;
    __syncthreads();
    int nw = blockDim.x >> 5;
    float s = (threadIdx.x < (unsigned)nw) ? red[threadIdx.x] : 0.f;
    if (w == 0) {
        #pragma unroll
        for (int o = 16; o; o >>= 1) s += __shfl_xor_sync(0xffffffffu, s, o);
        if (lane == 0) red[0] = s;
    }
    __syncthreads();
    return red[0];
}

// ---------------- FP16 tensor-core GEMM (BK=32, 5-stage cp.async) ------------
// C[z] (M x N) = A_cat[z] (M x K) * B[z]^T + bias; operands fp16 in gmem.
// K % 32 == 0, ksplit % 32 == 0, K/32 >= 4. out_half: 0 -> fp32 C, 1 -> fp16 C.
#define ROWB 80
#define TILEB (128 * ROWB)
#define STAGEB (2 * TILEB)
#define NSTAGE 5
#define GEMM_SMEM (NSTAGE * STAGEB)   // 102400 B

__global__ __launch_bounds__(256, 2)
void hgemm(int K, int ksplit,
           const __half* __restrict__ A,  int lda,  long long sAz,
           const __half* __restrict__ A2, int lda2, long long sA2z,
           const __half* __restrict__ BT, int ldb,  long long sBz,
           const float* __restrict__ bias,
           void* __restrict__ Cv, int ldc, long long sCz, int out_half)
{
    extern __shared__ char smem[];

    const int z = blockIdx.z;
    A  += (size_t)z * sAz;
    A2 += (size_t)z * sA2z;
    BT += (size_t)z * sBz;

    const int row0 = blockIdx.y * 128;
    const int col0 = blockIdx.x * 128;
    const int tid  = threadIdx.x;
    const int lane = tid & 31;
    const int warp = tid >> 5;
    const int wm   = (warp >> 2) * 64;
    const int wn   = (warp & 3) * 32;
    const int g    = lane >> 2;
    const int c    = lane & 3;

    const uint32_t sb = (uint32_t)__cvta_generic_to_shared(smem);

    // ldmatrix lane address offsets (within a stage)
    const int lane15 = lane & 15;
    const int laneh  = lane >> 4;
    uint32_t aoff[4], boff[2];
    #pragma unroll
    for (int mt = 0; mt < 4; mt++)
        aoff[mt] = (uint32_t)((wm + mt * 16 + lane15) * ROWB + laneh * 16);
    #pragma unroll
    for (int np = 0; np < 2; np++)
        boff[np] = (uint32_t)(TILEB + (wn + np * 16 + lane15) * ROWB + laneh * 16);

    // loader mapping
    const int am = tid >> 1;
    const int ah = tid & 1;
    const int T = K / 32;

    auto issue_tile = [&](int t) {
        const int k0 = t * 32;
        const __half* Asrc; int kloc, ldA;
        if (k0 < ksplit) { Asrc = A;  kloc = k0;          ldA = lda;  }
        else             { Asrc = A2; kloc = k0 - ksplit; ldA = lda2; }
        const __half* ap = Asrc + (size_t)(row0 + am) * ldA + kloc + ah * 16;
        const __half* bp = BT + (size_t)(col0 + am) * ldb + k0 + ah * 16;
        uint32_t s = sb + (uint32_t)(t % NSTAGE) * STAGEB + (uint32_t)(am * ROWB + ah * 32);
        CP_ASYNC16(s,              ap);
        CP_ASYNC16(s + 16,         ap + 8);
        CP_ASYNC16(s + TILEB,      bp);
        CP_ASYNC16(s + TILEB + 16, bp + 8);
        CP_COMMIT();
    };

    float acc[4][4][4];
    #pragma unroll
    for (int mt = 0; mt < 4; mt++)
        #pragma unroll
        for (int nt = 0; nt < 4; nt++)
            #pragma unroll
            for (int r = 0; r < 4; r++) acc[mt][nt][r] = 0.f;

    // prologue: prefetch 4 tiles (all our K have T >= 4)
    issue_tile(0);
    issue_tile(1);
    issue_tile(2);
    issue_tile(3);

    for (int t = 0; t < T; t++) {
        CP_WAIT3();                    // tile t complete (4 groups always in flight)
        __syncthreads();

        const uint32_t base = sb + (uint32_t)(t % NSTAGE) * STAGEB;

        #pragma unroll
        for (int k16 = 0; k16 < 2; k16++) {
            const uint32_t ko = k16 * 32;
            uint32_t bf[4][2];
            LDSM4(bf[0][0], bf[1][0], bf[0][1], bf[1][1], base + boff[0] + ko);
            LDSM4(bf[2][0], bf[3][0], bf[2][1], bf[3][1], base + boff[1] + ko);
            #pragma unroll
            for (int mt = 0; mt < 4; mt++) {
                uint32_t a0, a1, a2, a3;
                LDSM4(a0, a1, a2, a3, base + aoff[mt] + ko);
                #pragma unroll
                for (int nt = 0; nt < 4; nt++)
                    mma_f16(acc[mt][nt][0], acc[mt][nt][1], acc[mt][nt][2], acc[mt][nt][3],
                            a0, a1, a2, a3, bf[nt][0], bf[nt][1]);
            }
        }

        if (t + 4 < T) issue_tile(t + 4);
        else           CP_COMMIT();    // keep group count invariant for CP_WAIT3
    }

    // ---- epilogue ----
    if (out_half) {
        __half* C = (__half*)Cv + (size_t)z * sCz;
        #pragma unroll
        for (int mt = 0; mt < 4; mt++) {
            int row = row0 + wm + mt * 16 + g;
            #pragma unroll
            for (int nt = 0; nt < 4; nt++) {
                int col = col0 + wn + nt * 8 + 2 * c;
                __half2 h0 = __floats2half2_rn(acc[mt][nt][0], acc[mt][nt][1]);
                __half2 h1 = __floats2half2_rn(acc[mt][nt][2], acc[mt][nt][3]);
                *(__half2*)(C + (size_t)row * ldc + col)       = h0;
                *(__half2*)(C + (size_t)(row + 8) * ldc + col) = h1;
            }
        }
    } else {
        float* C = (float*)Cv + (size_t)z * sCz;
        #pragma unroll
        for (int mt = 0; mt < 4; mt++) {
            int row = row0 + wm + mt * 16 + g;
            #pragma unroll
            for (int nt = 0; nt < 4; nt++) {
                int col = col0 + wn + nt * 8 + 2 * c;
                float b0 = bias ? bias[col]     : 0.f;
                float b1 = bias ? bias[col + 1] : 0.f;
                float2 v0 = make_float2(acc[mt][nt][0] + b0, acc[mt][nt][1] + b1);
                float2 v1 = make_float2(acc[mt][nt][2] + b0, acc[mt][nt][3] + b1);
                *(float2*)(C + (size_t)row * ldc + col)       = v0;
                *(float2*)(C + (size_t)(row + 8) * ldc + col) = v1;
            }
        }
    }
}

// ---------------- weight transpose + fp16 convert ([R][C] -> half [C][R]) ----
__global__ __launch_bounds__(256)
void transpose_h(const float* __restrict__ in, __half* __restrict__ out, int R, int C)
{
    __shared__ float t[32][33];
    const int z = blockIdx.z;
    in  += (size_t)z * R * C;
    out += (size_t)z * R * C;
    int c0 = blockIdx.x * 32, r0 = blockIdx.y * 32;
    int tx = threadIdx.x & 31, ty = threadIdx.x >> 5;
    #pragma unroll
    for (int j = 0; j < 4; j++)
        t[ty + j * 8][tx] = in[(size_t)(r0 + ty + j * 8) * C + c0 + tx];
    __syncthreads();
    #pragma unroll
    for (int j = 0; j < 4; j++)
        out[(size_t)(c0 + ty + j * 8) * R + r0 + tx] = __float2half_rn(t[tx][ty + j * 8]);
}

// ---------------- fp32 -> fp16 elementwise convert ---------------------------
__global__ __launch_bounds__(256)
void f2h(const float* __restrict__ in, __half* __restrict__ out, size_t n4)
{
    size_t i = (size_t)blockIdx.x * blockDim.x + threadIdx.x;
    if (i >= n4) return;
    float4 v = *(const float4*)(in + i * 4);
    __half2 h0 = __floats2half2_rn(v.x, v.y);
    __half2 h1 = __floats2half2_rn(v.z, v.w);
    *(uint2*)(out + i * 4) = make_uint2(*(uint32_t*)&h0, *(uint32_t*)&h1);
}

// ---------------- tiny action GEMM (K=32) ------------------------------------
__global__ __launch_bounds__(256)
void act_gemm(const float* __restrict__ action, const float* __restrict__ W3,
              const float* __restrict__ b3, float* __restrict__ xc)
{
    int b = blockIdx.x;
    __shared__ float a_s[ACTD];
    int t = threadIdx.x;
    if (t < ACTD) {
        float v = action[(size_t)b * ACTD + t];
        float m = fabsf(v); m = m > 1.f ? m : 1.f;
        a_s[t] = v / m;
    }
    __syncthreads();
    for (int n = t; n < HID; n += 256) {
        float s = b3[n];
        #pragma unroll
        for (int k = 0; k < ACTD; k++) s = fmaf(a_s[k], W3[k * HID + n], s);
        xc[(size_t)b * (3 * HID) + 2 * HID + n] = s;
    }
}

// ---------------- rmsnorm + silu -> fp16 --------------------------------------
__global__ __launch_bounds__(256)
void rms_silu(const float* __restrict__ xc, __half* __restrict__ xch,
              const float* __restrict__ w1, const float* __restrict__ w2,
              const float* __restrict__ w3)
{
    int b = blockIdx.x, s = blockIdx.y;
    const float* w = (s == 0) ? w1 : (s == 1) ? w2 : w3;
    const float* seg = xc + (size_t)b * (3 * HID) + (size_t)s * HID;
    __half* oseg = xch + (size_t)b * (3 * HID) + (size_t)s * HID;
    int i0 = threadIdx.x * 4;
    float4 v = *(const float4*)(seg + i0);
    float ss = v.x * v.x + v.y * v.y + v.z * v.z + v.w * v.w;
    float tot = block_sum(ss);
    float scale = rsqrtf(tot * (1.0f / HID) + EPSV);
    float4 g = *(const float4*)(w + i0);
    float o0, o1, o2, o3; float y;
    y = v.x * scale * g.x; o0 = y / (1.f + expf(-y));
    y = v.y * scale * g.y; o1 = y / (1.f + expf(-y));
    y = v.z * scale * g.z; o2 = y / (1.f + expf(-y));
    y = v.w * scale * g.w; o3 = y / (1.f + expf(-y));
    __half2 h0 = __floats2half2_rn(o0, o1);
    __half2 h1 = __floats2half2_rn(o2, o3);
    *(uint2*)(oseg + i0) = make_uint2(*(uint32_t*)&h0, *(uint32_t*)&h1);
}

// ---------------- rmsnorm over 8192 (fp16 in/out) ----------------------------
__global__ __launch_bounds__(256)
void rms_deter(const __half* __restrict__ H, const float* __restrict__ gdyn,
               __half* __restrict__ hnh)
{
    int b = blockIdx.x;
    const __half* row = H + (size_t)b * DETER;
    float v[32];
    float ss = 0.f;
    #pragma unroll
    for (int cc = 0; cc < 8; cc++) {
        int d = threadIdx.x * 4 + cc * 1024;
        uint2 u = *(const uint2*)(row + d);
        __half2 p0 = *(__half2*)&u.x, p1 = *(__half2*)&u.y;
        float2 f0 = __half22float2(p0), f1 = __half22float2(p1);
        v[cc * 4 + 0] = f0.x; v[cc * 4 + 1] = f0.y;
        v[cc * 4 + 2] = f1.x; v[cc * 4 + 3] = f1.y;
        ss += f0.x * f0.x + f0.y * f0.y + f1.x * f1.x + f1.y * f1.y;
    }
    float tot = block_sum(ss);
    float scale = rsqrtf(tot * (1.0f / DETER) + EPSV);
    __half* out = hnh + (size_t)b * DETER;
    #pragma unroll
    for (int cc = 0; cc < 8; cc++) {
        int d = threadIdx.x * 4 + cc * 1024;
        float4 g = *(const float4*)(gdyn + d);
        __half2 h0 = __floats2half2_rn(v[cc * 4 + 0] * scale * g.x, v[cc * 4 + 1] * scale * g.y);
        __half2 h1 = __floats2half2_rn(v[cc * 4 + 2] * scale * g.z, v[cc * 4 + 3] * scale * g.w);
        *(uint2*)(out + d) = make_uint2(*(uint32_t*)&h0, *(uint32_t*)&h1);
    }
}

// ---------------- gates (fp16 X) ---------------------------------------------
__device__ __forceinline__ float sigf(float x) { return 1.f / (1.f + expf(-x)); }

__global__ __launch_bounds__(256)
void gates(const __half* __restrict__ X, const float* __restrict__ deter,
           float* __restrict__ out)
{
    size_t t = (size_t)blockIdx.x * blockDim.x + threadIdx.x;
    size_t e = t * 4;
    int b = (int)(e / DETER);
    int d = (int)(e % DETER);
    int g = d >> 10, o = d & 1023;
    size_t xb = (size_t)b * (GRP * 3 * DPG) + (size_t)g * (3 * DPG) + o;

    uint2 uR = *(const uint2*)(X + xb);
    uint2 uC = *(const uint2*)(X + xb + DPG);
    uint2 uU = *(const uint2*)(X + xb + 2 * DPG);
    float4 D = *(const float4*)(deter + (size_t)b * DETER + d);

    float2 R0 = __half22float2(*(__half2*)&uR.x), R1 = __half22float2(*(__half2*)&uR.y);
    float2 C0 = __half22float2(*(__half2*)&uC.x), C1 = __half22float2(*(__half2*)&uC.y);
    float2 U0 = __half22float2(*(__half2*)&uU.x), U1 = __half22float2(*(__half2*)&uU.y);

    float4 r; float rs, cd, up;
    rs = sigf(R0.x); cd = tanhf(rs * C0.x); up = sigf(U0.x - 1.f); r.x = up * cd + (1.f - up) * D.x;
    rs = sigf(R0.y); cd = tanhf(rs * C0.y); up = sigf(U0.y - 1.f); r.y = up * cd + (1.f - up) * D.y;
    rs = sigf(R1.x); cd = tanhf(rs * C1.x); up = sigf(U1.x - 1.f); r.z = up * cd + (1.f - up) * D.z;
    rs = sigf(R1.y); cd = tanhf(rs * C1.y); up = sigf(U1.y - 1.f); r.w = up * cd + (1.f - up) * D.w;
    *(float4*)(out + e) = r;
}

// ---------------- launch -----------------------------------------------------
extern "C" void kernel_launch(void* const* d_in, const int* in_sizes, int n_in,
                              void* d_out, int out_size)
{
    const float* deter  = (const float*)d_in[0];
    const float* stoch  = (const float*)d_in[1];
    const float* action = (const float*)d_in[2];
    const float* W1     = (const float*)d_in[3];
    const float* b1     = (const float*)d_in[4];
    const float* W2     = (const float*)d_in[5];
    const float* b2     = (const float*)d_in[6];
    const float* W3     = (const float*)d_in[7];
    const float* b3     = (const float*)d_in[8];
    const float* g1     = (const float*)d_in[9];
    const float* g2     = (const float*)d_in[10];
    const float* g3     = (const float*)d_in[11];
    const float* Wdyn   = (const float*)d_in[12];
    const float* gdyn   = (const float*)d_in[13];
    const float* Wout   = (const float*)d_in[14];
    float* out          = (float*)d_out;

    float *xc;
    __half *Hh, *Xh, *xch, *hnh, *deterh, *stochh, *W1T, *W2T, *WdynT, *WoutT;
    cudaGetSymbolAddress((void**)&xc,     g_xc);
    cudaGetSymbolAddress((void**)&Hh,     g_Hh);
    cudaGetSymbolAddress((void**)&Xh,     g_Xh);
    cudaGetSymbolAddress((void**)&xch,    g_xch);
    cudaGetSymbolAddress((void**)&hnh,    g_hnh);
    cudaGetSymbolAddress((void**)&deterh, g_deterh);
    cudaGetSymbolAddress((void**)&stochh, g_stochh);
    cudaGetSymbolAddress((void**)&W1T,    g_W1T);
    cudaGetSymbolAddress((void**)&W2T,    g_W2T);
    cudaGetSymbolAddress((void**)&WdynT,  g_WdynT);
    cudaGetSymbolAddress((void**)&WoutT,  g_WoutT);

    cudaFuncSetAttribute(hgemm, cudaFuncAttributeMaxDynamicSharedMemorySize, GEMM_SMEM);

    // fp16 conversions of inputs + weight transposes
    f2h<<<(unsigned)((BSZ * (size_t)DETER / 4 + 255) / 256), 256>>>(deter, deterh, BSZ * (size_t)DETER / 4);
    f2h<<<(unsigned)((BSZ * (size_t)STOCH / 4 + 255) / 256), 256>>>(stoch, stochh, BSZ * (size_t)STOCH / 4);
    transpose_h<<<dim3(HID / 32, DETER / 32, 1), 256>>>(W1, W1T, DETER, HID);
    transpose_h<<<dim3(HID / 32, STOCH / 32, 1), 256>>>(W2, W2T, STOCH, HID);
    transpose_h<<<dim3(DPG / 32, 4096 / 32, GRP), 256>>>(Wdyn, WdynT, 4096, DPG);
    transpose_h<<<dim3(3 * DPG / 32, DPG / 32, GRP), 256>>>(Wout, WoutT, DPG, 3 * DPG);

    // GEMM1: deter @ W1 + b1 -> xc[:, 0:1024] (fp32)
    hgemm<<<dim3(HID / 128, BSZ / 128, 1), 256, GEMM_SMEM>>>(
        DETER, DETER, deterh, DETER, 0, deterh, DETER, 0,
        W1T, DETER, 0, b1, xc, 3 * HID, 0, 0);

    // GEMM2: stoch @ W2 + b2 -> xc[:, 1024:2048] (fp32)
    hgemm<<<dim3(HID / 128, BSZ / 128, 1), 256, GEMM_SMEM>>>(
        STOCH, STOCH, stochh, STOCH, 0, stochh, STOCH, 0,
        W2T, STOCH, 0, b2, xc + HID, 3 * HID, 0, 0);

    // GEMM3: norm(action) @ W3 + b3 -> xc[:, 2048:3072]
    act_gemm<<<BSZ, 256>>>(action, W3, b3, xc);

    // rmsnorm + silu -> fp16 activations
    rms_silu<<<dim3(BSZ, 3), 256>>>(xc, xch, g1, g2, g3);

    // GEMM4 (block-diagonal dyn): Hh = [xch | deter_g] @ Wdyn[g]  (fp16 out)
    hgemm<<<dim3(DPG / 128, BSZ / 128, GRP), 256, GEMM_SMEM>>>(
        4096, 3 * HID,
        xch, 3 * HID, 0,
        deterh, DETER, DPG,
        WdynT, 4096, (long long)DPG * 4096,
        nullptr, Hh, DETER, DPG, 1);

    // rmsnorm over 8192 -> fp16
    rms_deter<<<BSZ, 256>>>(Hh, gdyn, hnh);

    // GEMM5 (block-diagonal out): Xh[:, g, :] = hn_g @ Wout[g]  (fp16 out)
    hgemm<<<dim3(3 * DPG / 128, BSZ / 128, GRP), 256, GEMM_SMEM>>>(
        DPG, DPG,
        hnh, DETER, DPG,
        hnh, DETER, DPG,
        WoutT, DPG, (long long)3 * DPG * DPG,
        nullptr, Xh, GRP * 3 * DPG, 3 * DPG, 1);

    // gates
    size_t n4 = (size_t)BSZ * DETER / 4;
    gates<<<(unsigned)((n4 + 255) / 256), 256>>>(Xh, deter, out);
}

// round 12
// speedup vs baseline: 1.5054x; 1.5054x over previous
#include <cuda_runtime.h>
#include <cuda_fp16.h>
#include <math.h>
#include <stdint.h>

#define BSZ   2048
#define DETER 8192
#define STOCH 1024
#define ACTD  32
#define HID   1024
#define GRP   8
#define DPG   1024
#define EPSV  1e-6f

// ---------------- scratch (static device arrays; no allocations) -------------
__device__ float  g_xc [BSZ * 3 * HID];
__device__ __half g_Hh [BSZ * DETER];
__device__ __half g_Xh [BSZ * GRP * 3 * DPG];
__device__ __half g_xch[BSZ * 3 * HID];
__device__ __half g_hnh[BSZ * DETER];
__device__ __half g_deterh[BSZ * DETER];
__device__ __half g_stochh[BSZ * STOCH];
__device__ __half g_W1T  [HID * DETER];
__device__ __half g_W2T  [HID * STOCH];
__device__ __half g_WdynT[GRP * DPG * 4096];
__device__ __half g_WoutT[GRP * 3 * DPG * DPG];

// ---------------- helpers ----------------------------------------------------
__device__ __forceinline__ void mma_f16(float& c0, float& c1, float& c2, float& c3,
                                        uint32_t a0, uint32_t a1, uint32_t a2, uint32_t a3,
                                        uint32_t b0, uint32_t b1) {
    asm("mma.sync.aligned.m16n8k16.row.col.f32.f16.f16.f32 "
        "{%0,%1,%2,%3},{%4,%5,%6,%7},{%8,%9},{%0,%1,%2,%3};"
        : "+f"(c0), "+f"(c1), "+f"(c2), "+f"(c3)
        : "r"(a0), "r"(a1), "r"(a2), "r"(a3), "r"(b0), "r"(b1));
}

#define LDSM4(r0, r1, r2, r3, a) \
    asm volatile("ldmatrix.sync.aligned.m8n8.x4.shared.b16 {%0,%1,%2,%3}, [%4];" \
                 : "=r"(r0), "=r"(r1), "=r"(r2), "=r"(r3) : "r"(a))

#define CP_ASYNC16(s, g) \
    asm volatile("cp.async.cg.shared.global [%0], [%1], 16;" :: "r"(s), "l"(g) : "memory")
#define CP_COMMIT() asm volatile("cp.async.commit_group;" ::: "memory")
#define CP_WAIT2()  asm volatile("cp.async.wait_group 2;" ::: "memory")

__device__ __forceinline__ float block_sum(float v) {
    __shared__ float red[32];
    int lane = threadIdx.x & 31, w = threadIdx.x >> 5;
    #pragma unroll
    for (int o = 16; o; o >>= 1) v += __shfl_xor_sync(0xffffffffu, v, o);
    if (lane == 0) red[w] = v;
    __syncthreads();
    int nw = blockDim.x >> 5;
    float s = (threadIdx.x < (unsigned)nw) ? red[threadIdx.x] : 0.f;
    if (w == 0) {
        #pragma unroll
        for (int o = 16; o; o >>= 1) s += __shfl_xor_sync(0xffffffffu, s, o);
        if (lane == 0) red[0] = s;
    }
    __syncthreads();
    return red[0];
}

// ---------------- FP16 tensor-core GEMM (BK=32, 4-stage cp.async) ------------
// C[z] (M x N) = A_cat[z] (M x K) * B[z]^T + bias; operands fp16 in gmem.
// K % 32 == 0, ksplit % 32 == 0, K/32 >= 3. out_half: 0 -> fp32 C, 1 -> fp16 C.
#define ROWB 80
#define TILEB (128 * ROWB)
#define STAGEB (2 * TILEB)
#define NSTAGE 4
#define GEMM_SMEM (NSTAGE * STAGEB)   // 81920 B -> 2 CTAs/SM (163.8 KB < 228 KB)

__global__ __launch_bounds__(256, 2)
void hgemm(int K, int ksplit,
           const __half* __restrict__ A,  int lda,  long long sAz,
           const __half* __restrict__ A2, int lda2, long long sA2z,
           const __half* __restrict__ BT, int ldb,  long long sBz,
           const float* __restrict__ bias,
           void* __restrict__ Cv, int ldc, long long sCz, int out_half)
{
    extern __shared__ char smem[];

    const int z = blockIdx.z;
    A  += (size_t)z * sAz;
    A2 += (size_t)z * sA2z;
    BT += (size_t)z * sBz;

    const int row0 = blockIdx.y * 128;
    const int col0 = blockIdx.x * 128;
    const int tid  = threadIdx.x;
    const int lane = tid & 31;
    const int warp = tid >> 5;
    const int wm   = (warp >> 2) * 64;
    const int wn   = (warp & 3) * 32;
    const int g    = lane >> 2;
    const int c    = lane & 3;

    const uint32_t sb = (uint32_t)__cvta_generic_to_shared(smem);

    // ldmatrix lane address offsets (within a stage)
    const int lane15 = lane & 15;
    const int laneh  = lane >> 4;
    uint32_t aoff[4], boff[2];
    #pragma unroll
    for (int mt = 0; mt < 4; mt++)
        aoff[mt] = (uint32_t)((wm + mt * 16 + lane15) * ROWB + laneh * 16);
    #pragma unroll
    for (int np = 0; np < 2; np++)
        boff[np] = (uint32_t)(TILEB + (wn + np * 16 + lane15) * ROWB + laneh * 16);

    // loader mapping
    const int am = tid >> 1;
    const int ah = tid & 1;
    const int T = K / 32;

    auto issue_tile = [&](int t) {
        const int k0 = t * 32;
        const __half* Asrc; int kloc, ldA;
        if (k0 < ksplit) { Asrc = A;  kloc = k0;          ldA = lda;  }
        else             { Asrc = A2; kloc = k0 - ksplit; ldA = lda2; }
        const __half* ap = Asrc + (size_t)(row0 + am) * ldA + kloc + ah * 16;
        const __half* bp = BT + (size_t)(col0 + am) * ldb + k0 + ah * 16;
        uint32_t s = sb + (uint32_t)(t % NSTAGE) * STAGEB + (uint32_t)(am * ROWB + ah * 32);
        CP_ASYNC16(s,              ap);
        CP_ASYNC16(s + 16,         ap + 8);
        CP_ASYNC16(s + TILEB,      bp);
        CP_ASYNC16(s + TILEB + 16, bp + 8);
        CP_COMMIT();
    };

    float acc[4][4][4];
    #pragma unroll
    for (int mt = 0; mt < 4; mt++)
        #pragma unroll
        for (int nt = 0; nt < 4; nt++)
            #pragma unroll
            for (int r = 0; r < 4; r++) acc[mt][nt][r] = 0.f;

    // prologue: prefetch 3 tiles (all our K have T >= 3)
    issue_tile(0);
    issue_tile(1);
    issue_tile(2);

    for (int t = 0; t < T; t++) {
        CP_WAIT2();                    // tile t complete (3 groups in flight)
        __syncthreads();

        const uint32_t base = sb + (uint32_t)(t % NSTAGE) * STAGEB;

        #pragma unroll
        for (int k16 = 0; k16 < 2; k16++) {
            const uint32_t ko = k16 * 32;
            uint32_t bf[4][2];
            LDSM4(bf[0][0], bf[1][0], bf[0][1], bf[1][1], base + boff[0] + ko);
            LDSM4(bf[2][0], bf[3][0], bf[2][1], bf[3][1], base + boff[1] + ko);
            #pragma unroll
            for (int mt = 0; mt < 4; mt++) {
                uint32_t a0, a1, a2, a3;
                LDSM4(a0, a1, a2, a3, base + aoff[mt] + ko);
                #pragma unroll
                for (int nt = 0; nt < 4; nt++)
                    mma_f16(acc[mt][nt][0], acc[mt][nt][1], acc[mt][nt][2], acc[mt][nt][3],
                            a0, a1, a2, a3, bf[nt][0], bf[nt][1]);
            }
        }

        if (t + 3 < T) issue_tile(t + 3);
        else           CP_COMMIT();    // keep group count invariant for CP_WAIT2
    }

    // ---- epilogue ----
    if (out_half) {
        __half* C = (__half*)Cv + (size_t)z * sCz;
        #pragma unroll
        for (int mt = 0; mt < 4; mt++) {
            int row = row0 + wm + mt * 16 + g;
            #pragma unroll
            for (int nt = 0; nt < 4; nt++) {
                int col = col0 + wn + nt * 8 + 2 * c;
                __half2 h0 = __floats2half2_rn(acc[mt][nt][0], acc[mt][nt][1]);
                __half2 h1 = __floats2half2_rn(acc[mt][nt][2], acc[mt][nt][3]);
                *(__half2*)(C + (size_t)row * ldc + col)       = h0;
                *(__half2*)(C + (size_t)(row + 8) * ldc + col) = h1;
            }
        }
    } else {
        float* C = (float*)Cv + (size_t)z * sCz;
        #pragma unroll
        for (int mt = 0; mt < 4; mt++) {
            int row = row0 + wm + mt * 16 + g;
            #pragma unroll
            for (int nt = 0; nt < 4; nt++) {
                int col = col0 + wn + nt * 8 + 2 * c;
                float b0 = bias ? bias[col]     : 0.f;
                float b1 = bias ? bias[col + 1] : 0.f;
                float2 v0 = make_float2(acc[mt][nt][0] + b0, acc[mt][nt][1] + b1);
                float2 v1 = make_float2(acc[mt][nt][2] + b0, acc[mt][nt][3] + b1);
                *(float2*)(C + (size_t)row * ldc + col)       = v0;
                *(float2*)(C + (size_t)(row + 8) * ldc + col) = v1;
            }
        }
    }
}

// ---------------- weight transpose + fp16 convert ([R][C] -> half [C][R]) ----
__global__ __launch_bounds__(256)
void transpose_h(const float* __restrict__ in, __half* __restrict__ out, int R, int C)
{
    __shared__ float t[32][33];
    const int z = blockIdx.z;
    in  += (size_t)z * R * C;
    out += (size_t)z * R * C;
    int c0 = blockIdx.x * 32, r0 = blockIdx.y * 32;
    int tx = threadIdx.x & 31, ty = threadIdx.x >> 5;
    #pragma unroll
    for (int j = 0; j < 4; j++)
        t[ty + j * 8][tx] = in[(size_t)(r0 + ty + j * 8) * C + c0 + tx];
    __syncthreads();
    #pragma unroll
    for (int j = 0; j < 4; j++)
        out[(size_t)(c0 + ty + j * 8) * R + r0 + tx] = __float2half_rn(t[tx][ty + j * 8]);
}

// ---------------- fp32 -> fp16 elementwise convert ---------------------------
__global__ __launch_bounds__(256)
void f2h(const float* __restrict__ in, __half* __restrict__ out, size_t n4)
{
    size_t i = (size_t)blockIdx.x * blockDim.x + threadIdx.x;
    if (i >= n4) return;
    float4 v = *(const float4*)(in + i * 4);
    __half2 h0 = __floats2half2_rn(v.x, v.y);
    __half2 h1 = __floats2half2_rn(v.z, v.w);
    *(uint2*)(out + i * 4) = make_uint2(*(uint32_t*)&h0, *(uint32_t*)&h1);
}

// ---------------- tiny action GEMM (K=32) ------------------------------------
__global__ __launch_bounds__(256)
void act_gemm(const float* __restrict__ action, const float* __restrict__ W3,
              const float* __restrict__ b3, float* __restrict__ xc)
{
    int b = blockIdx.x;
    __shared__ float a_s[ACTD];
    int t = threadIdx.x;
    if (t < ACTD) {
        float v = action[(size_t)b * ACTD + t];
        float m = fabsf(v); m = m > 1.f ? m : 1.f;
        a_s[t] = v / m;
    }
    __syncthreads();
    for (int n = t; n < HID; n += 256) {
        float s = b3[n];
        #pragma unroll
        for (int k = 0; k < ACTD; k++) s = fmaf(a_s[k], W3[k * HID + n], s);
        xc[(size_t)b * (3 * HID) + 2 * HID + n] = s;
    }
}

// ---------------- rmsnorm + silu -> fp16 --------------------------------------
__global__ __launch_bounds__(256)
void rms_silu(const float* __restrict__ xc, __half* __restrict__ xch,
              const float* __restrict__ w1, const float* __restrict__ w2,
              const float* __restrict__ w3)
{
    int b = blockIdx.x, s = blockIdx.y;
    const float* w = (s == 0) ? w1 : (s == 1) ? w2 : w3;
    const float* seg = xc + (size_t)b * (3 * HID) + (size_t)s * HID;
    __half* oseg = xch + (size_t)b * (3 * HID) + (size_t)s * HID;
    int i0 = threadIdx.x * 4;
    float4 v = *(const float4*)(seg + i0);
    float ss = v.x * v.x + v.y * v.y + v.z * v.z + v.w * v.w;
    float tot = block_sum(ss);
    float scale = rsqrtf(tot * (1.0f / HID) + EPSV);
    float4 g = *(const float4*)(w + i0);
    float o0, o1, o2, o3; float y;
    y = v.x * scale * g.x; o0 = y / (1.f + expf(-y));
    y = v.y * scale * g.y; o1 = y / (1.f + expf(-y));
    y = v.z * scale * g.z; o2 = y / (1.f + expf(-y));
    y = v.w * scale * g.w; o3 = y / (1.f + expf(-y));
    __half2 h0 = __floats2half2_rn(o0, o1);
    __half2 h1 = __floats2half2_rn(o2, o3);
    *(uint2*)(oseg + i0) = make_uint2(*(uint32_t*)&h0, *(uint32_t*)&h1);
}

// ---------------- rmsnorm over 8192 (fp16 in/out) ----------------------------
__global__ __launch_bounds__(256)
void rms_deter(const __half* __restrict__ H, const float* __restrict__ gdyn,
               __half* __restrict__ hnh)
{
    int b = blockIdx.x;
    const __half* row = H + (size_t)b * DETER;
    float v[32];
    float ss = 0.f;
    #pragma unroll
    for (int cc = 0; cc < 8; cc++) {
        int d = threadIdx.x * 4 + cc * 1024;
        uint2 u = *(const uint2*)(row + d);
        __half2 p0 = *(__half2*)&u.x, p1 = *(__half2*)&u.y;
        float2 f0 = __half22float2(p0), f1 = __half22float2(p1);
        v[cc * 4 + 0] = f0.x; v[cc * 4 + 1] = f0.y;
        v[cc * 4 + 2] = f1.x; v[cc * 4 + 3] = f1.y;
        ss += f0.x * f0.x + f0.y * f0.y + f1.x * f1.x + f1.y * f1.y;
    }
    float tot = block_sum(ss);
    float scale = rsqrtf(tot * (1.0f / DETER) + EPSV);
    __half* out = hnh + (size_t)b * DETER;
    #pragma unroll
    for (int cc = 0; cc < 8; cc++) {
        int d = threadIdx.x * 4 + cc * 1024;
        float4 g = *(const float4*)(gdyn + d);
        __half2 h0 = __floats2half2_rn(v[cc * 4 + 0] * scale * g.x, v[cc * 4 + 1] * scale * g.y);
        __half2 h1 = __floats2half2_rn(v[cc * 4 + 2] * scale * g.z, v[cc * 4 + 3] * scale * g.w);
        *(uint2*)(out + d) = make_uint2(*(uint32_t*)&h0, *(uint32_t*)&h1);
    }
}

// ---------------- gates (fp16 X) ---------------------------------------------
__device__ __forceinline__ float sigf(float x) { return 1.f / (1.f + expf(-x)); }

__global__ __launch_bounds__(256)
void gates(const __half* __restrict__ X, const float* __restrict__ deter,
           float* __restrict__ out)
{
    size_t t = (size_t)blockIdx.x * blockDim.x + threadIdx.x;
    size_t e = t * 4;
    int b = (int)(e / DETER);
    int d = (int)(e % DETER);
    int g = d >> 10, o = d & 1023;
    size_t xb = (size_t)b * (GRP * 3 * DPG) + (size_t)g * (3 * DPG) + o;

    uint2 uR = *(const uint2*)(X + xb);
    uint2 uC = *(const uint2*)(X + xb + DPG);
    uint2 uU = *(const uint2*)(X + xb + 2 * DPG);
    float4 D = *(const float4*)(deter + (size_t)b * DETER + d);

    float2 R0 = __half22float2(*(__half2*)&uR.x), R1 = __half22float2(*(__half2*)&uR.y);
    float2 C0 = __half22float2(*(__half2*)&uC.x), C1 = __half22float2(*(__half2*)&uC.y);
    float2 U0 = __half22float2(*(__half2*)&uU.x), U1 = __half22float2(*(__half2*)&uU.y);

    float4 r; float rs, cd, up;
    rs = sigf(R0.x); cd = tanhf(rs * C0.x); up = sigf(U0.x - 1.f); r.x = up * cd + (1.f - up) * D.x;
    rs = sigf(R0.y); cd = tanhf(rs * C0.y); up = sigf(U0.y - 1.f); r.y = up * cd + (1.f - up) * D.y;
    rs = sigf(R1.x); cd = tanhf(rs * C1.x); up = sigf(U1.x - 1.f); r.z = up * cd + (1.f - up) * D.z;
    rs = sigf(R1.y); cd = tanhf(rs * C1.y); up = sigf(U1.y - 1.f); r.w = up * cd + (1.f - up) * D.w;
    *(float4*)(out + e) = r;
}

// ---------------- launch -----------------------------------------------------
extern "C" void kernel_launch(void* const* d_in, const int* in_sizes, int n_in,
                              void* d_out, int out_size)
{
    const float* deter  = (const float*)d_in[0];
    const float* stoch  = (const float*)d_in[1];
    const float* action = (const float*)d_in[2];
    const float* W1     = (const float*)d_in[3];
    const float* b1     = (const float*)d_in[4];
    const float* W2     = (const float*)d_in[5];
    const float* b2     = (const float*)d_in[6];
    const float* W3     = (const float*)d_in[7];
    const float* b3     = (const float*)d_in[8];
    const float* g1     = (const float*)d_in[9];
    const float* g2     = (const float*)d_in[10];
    const float* g3     = (const float*)d_in[11];
    const float* Wdyn   = (const float*)d_in[12];
    const float* gdyn   = (const float*)d_in[13];
    const float* Wout   = (const float*)d_in[14];
    float* out          = (float*)d_out;

    float *xc;
    __half *Hh, *Xh, *xch, *hnh, *deterh, *stochh, *W1T, *W2T, *WdynT, *WoutT;
    cudaGetSymbolAddress((void**)&xc,     g_xc);
    cudaGetSymbolAddress((void**)&Hh,     g_Hh);
    cudaGetSymbolAddress((void**)&Xh,     g_Xh);
    cudaGetSymbolAddress((void**)&xch,    g_xch);
    cudaGetSymbolAddress((void**)&hnh,    g_hnh);
    cudaGetSymbolAddress((void**)&deterh, g_deterh);
    cudaGetSymbolAddress((void**)&stochh, g_stochh);
    cudaGetSymbolAddress((void**)&W1T,    g_W1T);
    cudaGetSymbolAddress((void**)&W2T,    g_W2T);
    cudaGetSymbolAddress((void**)&WdynT,  g_WdynT);
    cudaGetSymbolAddress((void**)&WoutT,  g_WoutT);

    cudaFuncSetAttribute(hgemm, cudaFuncAttributeMaxDynamicSharedMemorySize, GEMM_SMEM);

    // fp16 conversions of inputs + weight transposes
    f2h<<<(unsigned)((BSZ * (size_t)DETER / 4 + 255) / 256), 256>>>(deter, deterh, BSZ * (size_t)DETER / 4);
    f2h<<<(unsigned)((BSZ * (size_t)STOCH / 4 + 255) / 256), 256>>>(stoch, stochh, BSZ * (size_t)STOCH / 4);
    transpose_h<<<dim3(HID / 32, DETER / 32, 1), 256>>>(W1, W1T, DETER, HID);
    transpose_h<<<dim3(HID / 32, STOCH / 32, 1), 256>>>(W2, W2T, STOCH, HID);
    transpose_h<<<dim3(DPG / 32, 4096 / 32, GRP), 256>>>(Wdyn, WdynT, 4096, DPG);
    transpose_h<<<dim3(3 * DPG / 32, DPG / 32, GRP), 256>>>(Wout, WoutT, DPG, 3 * DPG);

    // GEMM1: deter @ W1 + b1 -> xc[:, 0:1024] (fp32)
    hgemm<<<dim3(HID / 128, BSZ / 128, 1), 256, GEMM_SMEM>>>(
        DETER, DETER, deterh, DETER, 0, deterh, DETER, 0,
        W1T, DETER, 0, b1, xc, 3 * HID, 0, 0);

    // GEMM2: stoch @ W2 + b2 -> xc[:, 1024:2048] (fp32)
    hgemm<<<dim3(HID / 128, BSZ / 128, 1), 256, GEMM_SMEM>>>(
        STOCH, STOCH, stochh, STOCH, 0, stochh, STOCH, 0,
        W2T, STOCH, 0, b2, xc + HID, 3 * HID, 0, 0);

    // GEMM3: norm(action) @ W3 + b3 -> xc[:, 2048:3072]
    act_gemm<<<BSZ, 256>>>(action, W3, b3, xc);

    // rmsnorm + silu -> fp16 activations
    rms_silu<<<dim3(BSZ, 3), 256>>>(xc, xch, g1, g2, g3);

    // GEMM4 (block-diagonal dyn): Hh = [xch | deter_g] @ Wdyn[g]  (fp16 out)
    hgemm<<<dim3(DPG / 128, BSZ / 128, GRP), 256, GEMM_SMEM>>>(
        4096, 3 * HID,
        xch, 3 * HID, 0,
        deterh, DETER, DPG,
        WdynT, 4096, (long long)DPG * 4096,
        nullptr, Hh, DETER, DPG, 1);

    // rmsnorm over 8192 -> fp16
    rms_deter<<<BSZ, 256>>>(Hh, gdyn, hnh);

    // GEMM5 (block-diagonal out): Xh[:, g, :] = hn_g @ Wout[g]  (fp16 out)
    hgemm<<<dim3(3 * DPG / 128, BSZ / 128, GRP), 256, GEMM_SMEM>>>(
        DPG, DPG,
        hnh, DETER, DPG,
        hnh, DETER, DPG,
        WoutT, DPG, (long long)3 * DPG * DPG,
        nullptr, Xh, GRP * 3 * DPG, 3 * DPG, 1);

    // gates
    size_t n4 = (size_t)BSZ * DETER / 4;
    gates<<<(unsigned)((n4 + 255) / 256), 256>>>(Xh, deter, out);
}

// round 13
// speedup vs baseline: 1.5182x; 1.0085x over previous
#include <cuda_runtime.h>
#include <cuda_fp16.h>
#include <math.h>
#include <stdint.h>

#define BSZ   2048
#define DETER 8192
#define STOCH 1024
#define ACTD  32
#define HID   1024
#define GRP   8
#define DPG   1024
#define EPSV  1e-6f

// ---------------- scratch (static device arrays; no allocations) -------------
__device__ float  g_xc [BSZ * 3 * HID];
__device__ __half g_Hh [BSZ * DETER];
__device__ __half g_Xh [BSZ * GRP * 3 * DPG];
__device__ __half g_xch[BSZ * 3 * HID];
__device__ __half g_hnh[BSZ * DETER];
__device__ __half g_deterh[BSZ * DETER];
__device__ __half g_stochh[BSZ * STOCH];
__device__ __half g_W1T  [HID * DETER];
__device__ __half g_W2T  [HID * STOCH];
__device__ __half g_WdynT[GRP * DPG * 4096];
__device__ __half g_WoutT[GRP * 3 * DPG * DPG];

// ---------------- helpers ----------------------------------------------------
__device__ __forceinline__ void mma_f16(float& c0, float& c1, float& c2, float& c3,
                                        uint32_t a0, uint32_t a1, uint32_t a2, uint32_t a3,
                                        uint32_t b0, uint32_t b1) {
    asm("mma.sync.aligned.m16n8k16.row.col.f32.f16.f16.f32 "
        "{%0,%1,%2,%3},{%4,%5,%6,%7},{%8,%9},{%0,%1,%2,%3};"
        : "+f"(c0), "+f"(c1), "+f"(c2), "+f"(c3)
        : "r"(a0), "r"(a1), "r"(a2), "r"(a3), "r"(b0), "r"(b1));
}

#define LDSM4(r0, r1, r2, r3, a) \
    asm volatile("ldmatrix.sync.aligned.m8n8.x4.shared.b16 {%0,%1,%2,%3}, [%4];" \
                 : "=r"(r0), "=r"(r1), "=r"(r2), "=r"(r3) : "r"(a))

#define CP_ASYNC16(s, g) \
    asm volatile("cp.async.cg.shared.global [%0], [%1], 16;" :: "r"(s), "l"(g) : "memory")
#define CP_COMMIT() asm volatile("cp.async.commit_group;" ::: "memory")
#define CP_WAIT2()  asm volatile("cp.async.wait_group 2;" ::: "memory")

__device__ __forceinline__ float block_sum(float v) {
    __shared__ float red[32];
    int lane = threadIdx.x & 31, w = threadIdx.x >> 5;
    #pragma unroll
    for (int o = 16; o; o >>= 1) v += __shfl_xor_sync(0xffffffffu, v, o);
    if (lane == 0) red[w] = v;
    __syncthreads();
    int nw = blockDim.x >> 5;
    float s = (threadIdx.x < (unsigned)nw) ? red[threadIdx.x] : 0.f;
    if (w == 0) {
        #pragma unroll
        for (int o = 16; o; o >>= 1) s += __shfl_xor_sync(0xffffffffu, s, o);
        if (lane == 0) red[0] = s;
    }
    __syncthreads();
    return red[0];
}

// ---------------- FP16 tensor-core GEMM (BM=128, BN=64, 4-stage) -------------
// C[z] (M x N) = A_cat[z] (M x K) * B[z]^T + bias; operands fp16 in gmem.
// K % 32 == 0, ksplit % 32 == 0, K/32 >= 3. out_half: 0 -> fp32 C, 1 -> fp16 C.
#define ROWB 80
#define ATILEB (128 * ROWB)                 // 10240 B
#define BTILEB (64 * ROWB)                  // 5120 B
#define STAGEB (ATILEB + BTILEB)            // 15360 B
#define NSTAGE 4
#define GEMM_SMEM (NSTAGE * STAGEB)         // 61440 B -> 2 CTAs/SM

__global__ __launch_bounds__(256, 2)
void hgemm(int K, int ksplit,
           const __half* __restrict__ A,  int lda,  long long sAz,
           const __half* __restrict__ A2, int lda2, long long sA2z,
           const __half* __restrict__ BT, int ldb,  long long sBz,
           const float* __restrict__ bias,
           void* __restrict__ Cv, int ldc, long long sCz, int out_half)
{
    extern __shared__ char smem[];

    const int z = blockIdx.z;
    A  += (size_t)z * sAz;
    A2 += (size_t)z * sA2z;
    BT += (size_t)z * sBz;

    const int row0 = blockIdx.y * 128;
    const int col0 = blockIdx.x * 64;
    const int tid  = threadIdx.x;
    const int lane = tid & 31;
    const int warp = tid >> 5;
    const int wm   = (warp >> 1) * 32;      // 0,32,64,96
    const int wn   = (warp & 1) * 32;       // 0,32
    const int g    = lane >> 2;
    const int c    = lane & 3;

    const uint32_t sb = (uint32_t)__cvta_generic_to_shared(smem);

    // ldmatrix lane address offsets (within a stage)
    const int lane15 = lane & 15;
    const int laneh  = lane >> 4;
    uint32_t aoff[2], boff[2];
    #pragma unroll
    for (int mt = 0; mt < 2; mt++)
        aoff[mt] = (uint32_t)((wm + mt * 16 + lane15) * ROWB + laneh * 16);
    #pragma unroll
    for (int np = 0; np < 2; np++)
        boff[np] = (uint32_t)(ATILEB + (wn + np * 16 + lane15) * ROWB + laneh * 16);

    // loader mapping
    const int am = tid >> 1;                // A row 0..127
    const int ah = tid & 1;
    const int T = K / 32;

    auto issue_tile = [&](int t) {
        const int k0 = t * 32;
        const __half* Asrc; int kloc, ldA;
        if (k0 < ksplit) { Asrc = A;  kloc = k0;          ldA = lda;  }
        else             { Asrc = A2; kloc = k0 - ksplit; ldA = lda2; }
        const uint32_t st = sb + (uint32_t)(t % NSTAGE) * STAGEB;
        const __half* ap = Asrc + (size_t)(row0 + am) * ldA + kloc + ah * 16;
        uint32_t s = st + (uint32_t)(am * ROWB + ah * 32);
        CP_ASYNC16(s,      ap);
        CP_ASYNC16(s + 16, ap + 8);
        if (tid < 128) {                    // B rows 0..63
            const int bm = tid >> 1, bh = tid & 1;
            const __half* bp = BT + (size_t)(col0 + bm) * ldb + k0 + bh * 16;
            uint32_t sB = st + ATILEB + (uint32_t)(bm * ROWB + bh * 32);
            CP_ASYNC16(sB,      bp);
            CP_ASYNC16(sB + 16, bp + 8);
        }
        CP_COMMIT();
    };

    float acc[2][4][4];
    #pragma unroll
    for (int mt = 0; mt < 2; mt++)
        #pragma unroll
        for (int nt = 0; nt < 4; nt++)
            #pragma unroll
            for (int r = 0; r < 4; r++) acc[mt][nt][r] = 0.f;

    // prologue: prefetch 3 tiles (all our K have T >= 3)
    issue_tile(0);
    issue_tile(1);
    issue_tile(2);

    for (int t = 0; t < T; t++) {
        CP_WAIT2();
        __syncthreads();

        const uint32_t base = sb + (uint32_t)(t % NSTAGE) * STAGEB;

        #pragma unroll
        for (int k16 = 0; k16 < 2; k16++) {
            const uint32_t ko = k16 * 32;
            uint32_t bf[4][2];
            LDSM4(bf[0][0], bf[1][0], bf[0][1], bf[1][1], base + boff[0] + ko);
            LDSM4(bf[2][0], bf[3][0], bf[2][1], bf[3][1], base + boff[1] + ko);
            #pragma unroll
            for (int mt = 0; mt < 2; mt++) {
                uint32_t a0, a1, a2, a3;
                LDSM4(a0, a1, a2, a3, base + aoff[mt] + ko);
                #pragma unroll
                for (int nt = 0; nt < 4; nt++)
                    mma_f16(acc[mt][nt][0], acc[mt][nt][1], acc[mt][nt][2], acc[mt][nt][3],
                            a0, a1, a2, a3, bf[nt][0], bf[nt][1]);
            }
        }

        if (t + 3 < T) issue_tile(t + 3);
        else           CP_COMMIT();         // keep group count invariant
    }

    // ---- epilogue ----
    if (out_half) {
        __half* C = (__half*)Cv + (size_t)z * sCz;
        #pragma unroll
        for (int mt = 0; mt < 2; mt++) {
            int row = row0 + wm + mt * 16 + g;
            #pragma unroll
            for (int nt = 0; nt < 4; nt++) {
                int col = col0 + wn + nt * 8 + 2 * c;
                __half2 h0 = __floats2half2_rn(acc[mt][nt][0], acc[mt][nt][1]);
                __half2 h1 = __floats2half2_rn(acc[mt][nt][2], acc[mt][nt][3]);
                *(__half2*)(C + (size_t)row * ldc + col)       = h0;
                *(__half2*)(C + (size_t)(row + 8) * ldc + col) = h1;
            }
        }
    } else {
        float* C = (float*)Cv + (size_t)z * sCz;
        #pragma unroll
        for (int mt = 0; mt < 2; mt++) {
            int row = row0 + wm + mt * 16 + g;
            #pragma unroll
            for (int nt = 0; nt < 4; nt++) {
                int col = col0 + wn + nt * 8 + 2 * c;
                float b0 = bias ? bias[col]     : 0.f;
                float b1 = bias ? bias[col + 1] : 0.f;
                float2 v0 = make_float2(acc[mt][nt][0] + b0, acc[mt][nt][1] + b1);
                float2 v1 = make_float2(acc[mt][nt][2] + b0, acc[mt][nt][3] + b1);
                *(float2*)(C + (size_t)row * ldc + col)       = v0;
                *(float2*)(C + (size_t)(row + 8) * ldc + col) = v1;
            }
        }
    }
}

// ---------------- weight transpose + fp16 convert ([R][C] -> half [C][R]) ----
__global__ __launch_bounds__(256)
void transpose_h(const float* __restrict__ in, __half* __restrict__ out, int R, int C)
{
    __shared__ float t[32][33];
    const int z = blockIdx.z;
    in  += (size_t)z * R * C;
    out += (size_t)z * R * C;
    int c0 = blockIdx.x * 32, r0 = blockIdx.y * 32;
    int tx = threadIdx.x & 31, ty = threadIdx.x >> 5;
    #pragma unroll
    for (int j = 0; j < 4; j++)
        t[ty + j * 8][tx] = in[(size_t)(r0 + ty + j * 8) * C + c0 + tx];
    __syncthreads();
    #pragma unroll
    for (int j = 0; j < 4; j++)
        out[(size_t)(c0 + ty + j * 8) * R + r0 + tx] = __float2half_rn(t[tx][ty + j * 8]);
}

// ---------------- fp32 -> fp16 elementwise convert ---------------------------
__global__ __launch_bounds__(256)
void f2h(const float* __restrict__ in, __half* __restrict__ out, size_t n4)
{
    size_t i = (size_t)blockIdx.x * blockDim.x + threadIdx.x;
    if (i >= n4) return;
    float4 v = *(const float4*)(in + i * 4);
    __half2 h0 = __floats2half2_rn(v.x, v.y);
    __half2 h1 = __floats2half2_rn(v.z, v.w);
    *(uint2*)(out + i * 4) = make_uint2(*(uint32_t*)&h0, *(uint32_t*)&h1);
}

// ---------------- tiny action GEMM (K=32) ------------------------------------
__global__ __launch_bounds__(256)
void act_gemm(const float* __restrict__ action, const float* __restrict__ W3,
              const float* __restrict__ b3, float* __restrict__ xc)
{
    int b = blockIdx.x;
    __shared__ float a_s[ACTD];
    int t = threadIdx.x;
    if (t < ACTD) {
        float v = action[(size_t)b * ACTD + t];
        float m = fabsf(v); m = m > 1.f ? m : 1.f;
        a_s[t] = v / m;
    }
    __syncthreads();
    for (int n = t; n < HID; n += 256) {
        float s = b3[n];
        #pragma unroll
        for (int k = 0; k < ACTD; k++) s = fmaf(a_s[k], W3[k * HID + n], s);
        xc[(size_t)b * (3 * HID) + 2 * HID + n] = s;
    }
}

// ---------------- rmsnorm + silu -> fp16 --------------------------------------
__global__ __launch_bounds__(256)
void rms_silu(const float* __restrict__ xc, __half* __restrict__ xch,
              const float* __restrict__ w1, const float* __restrict__ w2,
              const float* __restrict__ w3)
{
    int b = blockIdx.x, s = blockIdx.y;
    const float* w = (s == 0) ? w1 : (s == 1) ? w2 : w3;
    const float* seg = xc + (size_t)b * (3 * HID) + (size_t)s * HID;
    __half* oseg = xch + (size_t)b * (3 * HID) + (size_t)s * HID;
    int i0 = threadIdx.x * 4;
    float4 v = *(const float4*)(seg + i0);
    float ss = v.x * v.x + v.y * v.y + v.z * v.z + v.w * v.w;
    float tot = block_sum(ss);
    float scale = rsqrtf(tot * (1.0f / HID) + EPSV);
    float4 g = *(const float4*)(w + i0);
    float o0, o1, o2, o3; float y;
    y = v.x * scale * g.x; o0 = y / (1.f + expf(-y));
    y = v.y * scale * g.y; o1 = y / (1.f + expf(-y));
    y = v.z * scale * g.z; o2 = y / (1.f + expf(-y));
    y = v.w * scale * g.w; o3 = y / (1.f + expf(-y));
    __half2 h0 = __floats2half2_rn(o0, o1);
    __half2 h1 = __floats2half2_rn(o2, o3);
    *(uint2*)(oseg + i0) = make_uint2(*(uint32_t*)&h0, *(uint32_t*)&h1);
}

// ---------------- rmsnorm over 8192 (fp16 in/out) ----------------------------
__global__ __launch_bounds__(256)
void rms_deter(const __half* __restrict__ H, const float* __restrict__ gdyn,
               __half* __restrict__ hnh)
{
    int b = blockIdx.x;
    const __half* row = H + (size_t)b * DETER;
    float v[32];
    float ss = 0.f;
    #pragma unroll
    for (int cc = 0; cc < 8; cc++) {
        int d = threadIdx.x * 4 + cc * 1024;
        uint2 u = *(const uint2*)(row + d);
        __half2 p0 = *(__half2*)&u.x, p1 = *(__half2*)&u.y;
        float2 f0 = __half22float2(p0), f1 = __half22float2(p1);
        v[cc * 4 + 0] = f0.x; v[cc * 4 + 1] = f0.y;
        v[cc * 4 + 2] = f1.x; v[cc * 4 + 3] = f1.y;
        ss += f0.x * f0.x + f0.y * f0.y + f1.x * f1.x + f1.y * f1.y;
    }
    float tot = block_sum(ss);
    float scale = rsqrtf(tot * (1.0f / DETER) + EPSV);
    __half* out = hnh + (size_t)b * DETER;
    #pragma unroll
    for (int cc = 0; cc < 8; cc++) {
        int d = threadIdx.x * 4 + cc * 1024;
        float4 g = *(const float4*)(gdyn + d);
        __half2 h0 = __floats2half2_rn(v[cc * 4 + 0] * scale * g.x, v[cc * 4 + 1] * scale * g.y);
        __half2 h1 = __floats2half2_rn(v[cc * 4 + 2] * scale * g.z, v[cc * 4 + 3] * scale * g.w);
        *(uint2*)(out + d) = make_uint2(*(uint32_t*)&h0, *(uint32_t*)&h1);
    }
}

// ---------------- gates (fp16 X) ---------------------------------------------
__device__ __forceinline__ float sigf(float x) { return 1.f / (1.f + expf(-x)); }

__global__ __launch_bounds__(256)
void gates(const __half* __restrict__ X, const float* __restrict__ deter,
           float* __restrict__ out)
{
    size_t t = (size_t)blockIdx.x * blockDim.x + threadIdx.x;
    size_t e = t * 4;
    int b = (int)(e / DETER);
    int d = (int)(e % DETER);
    int g = d >> 10, o = d & 1023;
    size_t xb = (size_t)b * (GRP * 3 * DPG) + (size_t)g * (3 * DPG) + o;

    uint2 uR = *(const uint2*)(X + xb);
    uint2 uC = *(const uint2*)(X + xb + DPG);
    uint2 uU = *(const uint2*)(X + xb + 2 * DPG);
    float4 D = *(const float4*)(deter + (size_t)b * DETER + d);

    float2 R0 = __half22float2(*(__half2*)&uR.x), R1 = __half22float2(*(__half2*)&uR.y);
    float2 C0 = __half22float2(*(__half2*)&uC.x), C1 = __half22float2(*(__half2*)&uC.y);
    float2 U0 = __half22float2(*(__half2*)&uU.x), U1 = __half22float2(*(__half2*)&uU.y);

    float4 r; float rs, cd, up;
    rs = sigf(R0.x); cd = tanhf(rs * C0.x); up = sigf(U0.x - 1.f); r.x = up * cd + (1.f - up) * D.x;
    rs = sigf(R0.y); cd = tanhf(rs * C0.y); up = sigf(U0.y - 1.f); r.y = up * cd + (1.f - up) * D.y;
    rs = sigf(R1.x); cd = tanhf(rs * C1.x); up = sigf(U1.x - 1.f); r.z = up * cd + (1.f - up) * D.z;
    rs = sigf(R1.y); cd = tanhf(rs * C1.y); up = sigf(U1.y - 1.f); r.w = up * cd + (1.f - up) * D.w;
    *(float4*)(out + e) = r;
}

// ---------------- launch -----------------------------------------------------
extern "C" void kernel_launch(void* const* d_in, const int* in_sizes, int n_in,
                              void* d_out, int out_size)
{
    const float* deter  = (const float*)d_in[0];
    const float* stoch  = (const float*)d_in[1];
    const float* action = (const float*)d_in[2];
    const float* W1     = (const float*)d_in[3];
    const float* b1     = (const float*)d_in[4];
    const float* W2     = (const float*)d_in[5];
    const float* b2     = (const float*)d_in[6];
    const float* W3     = (const float*)d_in[7];
    const float* b3     = (const float*)d_in[8];
    const float* g1     = (const float*)d_in[9];
    const float* g2     = (const float*)d_in[10];
    const float* g3     = (const float*)d_in[11];
    const float* Wdyn   = (const float*)d_in[12];
    const float* gdyn   = (const float*)d_in[13];
    const float* Wout   = (const float*)d_in[14];
    float* out          = (float*)d_out;

    float *xc;
    __half *Hh, *Xh, *xch, *hnh, *deterh, *stochh, *W1T, *W2T, *WdynT, *WoutT;
    cudaGetSymbolAddress((void**)&xc,     g_xc);
    cudaGetSymbolAddress((void**)&Hh,     g_Hh);
    cudaGetSymbolAddress((void**)&Xh,     g_Xh);
    cudaGetSymbolAddress((void**)&xch,    g_xch);
    cudaGetSymbolAddress((void**)&hnh,    g_hnh);
    cudaGetSymbolAddress((void**)&deterh, g_deterh);
    cudaGetSymbolAddress((void**)&stochh, g_stochh);
    cudaGetSymbolAddress((void**)&W1T,    g_W1T);
    cudaGetSymbolAddress((void**)&W2T,    g_W2T);
    cudaGetSymbolAddress((void**)&WdynT,  g_WdynT);
    cudaGetSymbolAddress((void**)&WoutT,  g_WoutT);

    cudaFuncSetAttribute(hgemm, cudaFuncAttributeMaxDynamicSharedMemorySize, GEMM_SMEM);

    // fp16 conversions of inputs + weight transposes
    f2h<<<(unsigned)((BSZ * (size_t)DETER / 4 + 255) / 256), 256>>>(deter, deterh, BSZ * (size_t)DETER / 4);
    f2h<<<(unsigned)((BSZ * (size_t)STOCH / 4 + 255) / 256), 256>>>(stoch, stochh, BSZ * (size_t)STOCH / 4);
    transpose_h<<<dim3(HID / 32, DETER / 32, 1), 256>>>(W1, W1T, DETER, HID);
    transpose_h<<<dim3(HID / 32, STOCH / 32, 1), 256>>>(W2, W2T, STOCH, HID);
    transpose_h<<<dim3(DPG / 32, 4096 / 32, GRP), 256>>>(Wdyn, WdynT, 4096, DPG);
    transpose_h<<<dim3(3 * DPG / 32, DPG / 32, GRP), 256>>>(Wout, WoutT, DPG, 3 * DPG);

    // GEMM1: deter @ W1 + b1 -> xc[:, 0:1024] (fp32)
    hgemm<<<dim3(HID / 64, BSZ / 128, 1), 256, GEMM_SMEM>>>(
        DETER, DETER, deterh, DETER, 0, deterh, DETER, 0,
        W1T, DETER, 0, b1, xc, 3 * HID, 0, 0);

    // GEMM2: stoch @ W2 + b2 -> xc[:, 1024:2048] (fp32)
    hgemm<<<dim3(HID / 64, BSZ / 128, 1), 256, GEMM_SMEM>>>(
        STOCH, STOCH, stochh, STOCH, 0, stochh, STOCH, 0,
        W2T, STOCH, 0, b2, xc + HID, 3 * HID, 0, 0);

    // GEMM3: norm(action) @ W3 + b3 -> xc[:, 2048:3072]
    act_gemm<<<BSZ, 256>>>(action, W3, b3, xc);

    // rmsnorm + silu -> fp16 activations
    rms_silu<<<dim3(BSZ, 3), 256>>>(xc, xch, g1, g2, g3);

    // GEMM4 (block-diagonal dyn): Hh = [xch | deter_g] @ Wdyn[g]  (fp16 out)
    hgemm<<<dim3(DPG / 64, BSZ / 128, GRP), 256, GEMM_SMEM>>>(
        4096, 3 * HID,
        xch, 3 * HID, 0,
        deterh, DETER, DPG,
        WdynT, 4096, (long long)DPG * 4096,
        nullptr, Hh, DETER, DPG, 1);

    // rmsnorm over 8192 -> fp16
    rms_deter<<<BSZ, 256>>>(Hh, gdyn, hnh);

    // GEMM5 (block-diagonal out): Xh[:, g, :] = hn_g @ Wout[g]  (fp16 out)
    hgemm<<<dim3(3 * DPG / 64, BSZ / 128, GRP), 256, GEMM_SMEM>>>(
        DPG, DPG,
        hnh, DETER, DPG,
        hnh, DETER, DPG,
        WoutT, DPG, (long long)3 * DPG * DPG,
        nullptr, Xh, GRP * 3 * DPG, 3 * DPG, 1);

    // gates
    size_t n4 = (size_t)BSZ * DETER / 4;
    gates<<<(unsigned)((n4 + 255) / 256), 256>>>(Xh, deter, out);
}